// round 2
// baseline (speedup 1.0000x reference)
#include <cuda_runtime.h>
#include <math.h>

// Problem constants (fixed by reference setup_inputs)
#define BATCH   8
#define SEQ     2048
#define DIMS    1024
#define KV      128
#define OUTD    1152            // DIMS + KV
#define NROWS   (BATCH*SEQ)     // 16384
#define SCALE   0.08838834764831845f   // 1/sqrt(128)

// Attention tiling
#define BQ      64              // query rows per CTA
#define BK      64              // key rows per tile
#define HD      128             // head dim
#define PADQ    68              // padded stride for transposed tiles / P

// Scratch for projected keys/values (8 MB each) — static device arrays (no alloc)
__device__ float g_keys[NROWS * KV];
__device__ float g_vals[NROWS * KV];

// ---------------------------------------------------------------------------
// Kernel 1: copy minibatch into out[:, :, 0:1024]  (float4, grid-stride)
// ---------------------------------------------------------------------------
__global__ void copy_x_kernel(const float* __restrict__ x, float* __restrict__ out) {
    const int total4 = NROWS * (DIMS / 4);
    for (int idx = blockIdx.x * blockDim.x + threadIdx.x; idx < total4;
         idx += gridDim.x * blockDim.x) {
        int row = idx / (DIMS / 4);
        int c4  = idx % (DIMS / 4);
        float4 v = ((const float4*)x)[idx];
        *((float4*)(out + (size_t)row * OUTD) + c4) = v;
    }
}

// ---------------------------------------------------------------------------
// Kernel 2: projections  keys = X@Wk + bk ; values = X@Wv + bv
// Tile: 128 rows x 128 cols, BKc=16, 256 threads, 8x8 register tile.
// blockIdx.y: 0 -> keys, 1 -> values
// ---------------------------------------------------------------------------
__global__ __launch_bounds__(256, 2)
void proj_kernel(const float* __restrict__ x,
                 const float* __restrict__ Wkp, const float* __restrict__ bkp,
                 const float* __restrict__ Wvp, const float* __restrict__ bvp) {
    __shared__ float As[16][132];   // transposed A tile (k-major), padded
    __shared__ float Bs[16][128];   // W tile (already k-major in gmem)

    const float* W    = (blockIdx.y == 0) ? Wkp : Wvp;
    const float* bias = (blockIdx.y == 0) ? bkp : bvp;
    float*       outp = (blockIdx.y == 0) ? g_keys : g_vals;

    const int row0 = blockIdx.x * 128;
    const int tid  = threadIdx.x;
    const int tm   = (tid / 16) * 8;     // output row group
    const int tn   = (tid % 16) * 8;     // output col group

    // A-load mapping: each thread loads X[row0+am][kc+ak .. kc+ak+7]
    const int am = tid / 2;
    const int ak = (tid % 2) * 8;
    // B-load mapping: each thread loads W[kc+bkr][bn .. bn+7]
    const int bkr = tid / 16;
    const int bn  = (tid % 16) * 8;

    float acc[8][8];
    #pragma unroll
    for (int i = 0; i < 8; i++)
        #pragma unroll
        for (int j = 0; j < 8; j++) acc[i][j] = 0.0f;

    for (int kc = 0; kc < DIMS; kc += 16) {
        // load A tile (transposed into As[k][m])
        const float* xp = x + (size_t)(row0 + am) * DIMS + kc + ak;
        float4 a0 = *(const float4*)xp;
        float4 a1 = *(const float4*)(xp + 4);
        As[ak + 0][am] = a0.x; As[ak + 1][am] = a0.y;
        As[ak + 2][am] = a0.z; As[ak + 3][am] = a0.w;
        As[ak + 4][am] = a1.x; As[ak + 5][am] = a1.y;
        As[ak + 6][am] = a1.z; As[ak + 7][am] = a1.w;
        // load B tile (direct)
        const float* wp = W + (size_t)(kc + bkr) * KV + bn;
        *(float4*)&Bs[bkr][bn]     = *(const float4*)wp;
        *(float4*)&Bs[bkr][bn + 4] = *(const float4*)(wp + 4);
        __syncthreads();

        #pragma unroll
        for (int k = 0; k < 16; k++) {
            float a[8], bb[8];
            *(float4*)&a[0]  = *(const float4*)&As[k][tm];
            *(float4*)&a[4]  = *(const float4*)&As[k][tm + 4];
            *(float4*)&bb[0] = *(const float4*)&Bs[k][tn];
            *(float4*)&bb[4] = *(const float4*)&Bs[k][tn + 4];
            #pragma unroll
            for (int i = 0; i < 8; i++)
                #pragma unroll
                for (int j = 0; j < 8; j++)
                    acc[i][j] += a[i] * bb[j];
        }
        __syncthreads();
    }

    float bb[8];
    *(float4*)&bb[0] = *(const float4*)&bias[tn];
    *(float4*)&bb[4] = *(const float4*)&bias[tn + 4];
    #pragma unroll
    for (int i = 0; i < 8; i++) {
        float* op = outp + (size_t)(row0 + tm + i) * KV + tn;
        float4 r0, r1;
        r0.x = acc[i][0] + bb[0]; r0.y = acc[i][1] + bb[1];
        r0.z = acc[i][2] + bb[2]; r0.w = acc[i][3] + bb[3];
        r1.x = acc[i][4] + bb[4]; r1.y = acc[i][5] + bb[5];
        r1.z = acc[i][6] + bb[6]; r1.w = acc[i][7] + bb[7];
        *(float4*)op       = r0;
        *(float4*)(op + 4) = r1;
    }
}

// ---------------------------------------------------------------------------
// Kernel 3: causal attention with online softmax (flash-attention style)
// One CTA per (batch, 64-query block). 256 threads.
// smem: Qt[128][68], Kt[128][68] (k-major transposed), Vs[64][128],
//       Ps[64][68], m/l/alpha[64]  -> ~120.6 KB dynamic smem (1 CTA/SM)
// ---------------------------------------------------------------------------
#define SMEM_FLOATS (128*PADQ + 128*PADQ + BK*HD + BQ*PADQ + 3*BQ)
#define SMEM_BYTES  (SMEM_FLOATS * 4)

extern __shared__ float smem[];

__global__ __launch_bounds__(256, 1)
void attn_kernel(float* __restrict__ out) {
    const int bid = blockIdx.x;
    const int b   = bid % BATCH;
    const int qb  = (SEQ / BQ - 1) - bid / BATCH;   // heavy blocks first

    float* Qt   = smem;                  // [128][PADQ]  Qt[k][r]
    float* Kt   = Qt + 128 * PADQ;       // [128][PADQ]  Kt[k][c]
    float* Vs   = Kt + 128 * PADQ;       // [BK][HD]
    float* Ps   = Vs + BK * HD;          // [BQ][PADQ]
    float* mrow = Ps + BQ * PADQ;        // [BQ]
    float* lrow = mrow + BQ;             // [BQ]
    float* arow = lrow + BQ;             // [BQ]

    const int tid = threadIdx.x;
    const int ti  = tid / 16;            // 0..15
    const int tj  = tid % 16;            // 0..15
    const int rp  = ti * 4;              // row group (phase1 & phase2)
    const int cp  = tj * 8;              // col group (phase2, head dim)

    // ---- load Q tile transposed ----
    {
        const int r  = tid / 4;
        const int k0 = (tid % 4) * 32;
        const float* gq = g_keys + (size_t)(b * SEQ + qb * BQ + r) * KV + k0;
        #pragma unroll
        for (int i = 0; i < 32; i += 4) {
            float4 v = *(const float4*)(gq + i);
            Qt[(k0 + i + 0) * PADQ + r] = v.x;
            Qt[(k0 + i + 1) * PADQ + r] = v.y;
            Qt[(k0 + i + 2) * PADQ + r] = v.z;
            Qt[(k0 + i + 3) * PADQ + r] = v.w;
        }
    }
    if (tid < BQ) { mrow[tid] = -1e30f; lrow[tid] = 0.0f; }

    float o[4][8];
    #pragma unroll
    for (int i = 0; i < 4; i++)
        #pragma unroll
        for (int j = 0; j < 8; j++) o[i][j] = 0.0f;

    for (int kb = 0; kb <= qb; kb++) {
        __syncthreads();   // previous phase2 done (and Q-load / m-init on iter 0)

        // ---- load K tile (transposed) and V tile ----
        {
            const int r  = tid / 4;
            const int k0 = (tid % 4) * 32;
            const float* gk = g_keys + (size_t)(b * SEQ + kb * BK + r) * KV + k0;
            const float* gv = g_vals + (size_t)(b * SEQ + kb * BK + r) * KV + k0;
            #pragma unroll
            for (int i = 0; i < 32; i += 4) {
                float4 kvv = *(const float4*)(gk + i);
                Kt[(k0 + i + 0) * PADQ + r] = kvv.x;
                Kt[(k0 + i + 1) * PADQ + r] = kvv.y;
                Kt[(k0 + i + 2) * PADQ + r] = kvv.z;
                Kt[(k0 + i + 3) * PADQ + r] = kvv.w;
                *(float4*)&Vs[r * HD + k0 + i] = *(const float4*)(gv + i);
            }
        }
        __syncthreads();

        // ---- phase 1: S = (Q K^T) * scale, 4x4 register tile per thread ----
        float sacc[4][4];
        #pragma unroll
        for (int i = 0; i < 4; i++)
            #pragma unroll
            for (int j = 0; j < 4; j++) sacc[i][j] = 0.0f;

        #pragma unroll 4
        for (int k = 0; k < HD; k++) {
            float4 qv = *(const float4*)&Qt[k * PADQ + rp];
            float4 kv = *(const float4*)&Kt[k * PADQ + tj * 4];
            sacc[0][0] += qv.x * kv.x; sacc[0][1] += qv.x * kv.y;
            sacc[0][2] += qv.x * kv.z; sacc[0][3] += qv.x * kv.w;
            sacc[1][0] += qv.y * kv.x; sacc[1][1] += qv.y * kv.y;
            sacc[1][2] += qv.y * kv.z; sacc[1][3] += qv.y * kv.w;
            sacc[2][0] += qv.z * kv.x; sacc[2][1] += qv.z * kv.y;
            sacc[2][2] += qv.z * kv.z; sacc[2][3] += qv.z * kv.w;
            sacc[3][0] += qv.w * kv.x; sacc[3][1] += qv.w * kv.y;
            sacc[3][2] += qv.w * kv.z; sacc[3][3] += qv.w * kv.w;
        }

        // mask (causal) + write scores to Ps
        {
            const int cg = kb * BK + tj * 4;
            #pragma unroll
            for (int i = 0; i < 4; i++) {
                const int rg = qb * BQ + rp + i;
                float4 sv;
                sv.x = (cg + 0 > rg) ? -1e30f : sacc[i][0] * SCALE;
                sv.y = (cg + 1 > rg) ? -1e30f : sacc[i][1] * SCALE;
                sv.z = (cg + 2 > rg) ? -1e30f : sacc[i][2] * SCALE;
                sv.w = (cg + 3 > rg) ? -1e30f : sacc[i][3] * SCALE;
                *(float4*)&Ps[(rp + i) * PADQ + tj * 4] = sv;
            }
        }
        __syncthreads();

        // ---- online softmax: 4 threads per row ----
        {
            const int r    = tid / 4;
            const int part = tid % 4;
            float* prow = Ps + r * PADQ + part * 16;
            float tmax = -1e30f;
            #pragma unroll
            for (int j = 0; j < 16; j++) tmax = fmaxf(tmax, prow[j]);
            tmax = fmaxf(tmax, __shfl_xor_sync(0xffffffffu, tmax, 1));
            tmax = fmaxf(tmax, __shfl_xor_sync(0xffffffffu, tmax, 2));
            const float mold = mrow[r];
            const float mnew = fmaxf(mold, tmax);
            const float al   = __expf(mold - mnew);
            float sum = 0.0f;
            #pragma unroll
            for (int j = 0; j < 16; j++) {
                float p = __expf(prow[j] - mnew);
                prow[j] = p;
                sum += p;
            }
            sum += __shfl_xor_sync(0xffffffffu, sum, 1);
            sum += __shfl_xor_sync(0xffffffffu, sum, 2);
            if (part == 0) {
                mrow[r] = mnew;
                lrow[r] = lrow[r] * al + sum;
                arow[r] = al;
            }
        }
        __syncthreads();

        // ---- phase 2: O = O*alpha + P @ V, 4x8 register tile ----
        {
            const float a0 = arow[rp + 0], a1 = arow[rp + 1];
            const float a2 = arow[rp + 2], a3 = arow[rp + 3];
            #pragma unroll
            for (int j = 0; j < 8; j++) {
                o[0][j] *= a0; o[1][j] *= a1; o[2][j] *= a2; o[3][j] *= a3;
            }
            #pragma unroll 2
            for (int t = 0; t < BK; t += 4) {
                float pr[4][4];
                *(float4*)pr[0] = *(const float4*)&Ps[(rp + 0) * PADQ + t];
                *(float4*)pr[1] = *(const float4*)&Ps[(rp + 1) * PADQ + t];
                *(float4*)pr[2] = *(const float4*)&Ps[(rp + 2) * PADQ + t];
                *(float4*)pr[3] = *(const float4*)&Ps[(rp + 3) * PADQ + t];
                #pragma unroll
                for (int j = 0; j < 4; j++) {
                    const float* vp = &Vs[(t + j) * HD + cp];
                    float4 va = *(const float4*)vp;
                    float4 vb = *(const float4*)(vp + 4);
                    #pragma unroll
                    for (int i = 0; i < 4; i++) {
                        const float p = pr[i][j];
                        o[i][0] += p * va.x; o[i][1] += p * va.y;
                        o[i][2] += p * va.z; o[i][3] += p * va.w;
                        o[i][4] += p * vb.x; o[i][5] += p * vb.y;
                        o[i][6] += p * vb.z; o[i][7] += p * vb.w;
                    }
                }
            }
        }
    }

    // ---- epilogue: normalize and write out[:, :, 1024 + cp .. ] ----
    #pragma unroll
    for (int i = 0; i < 4; i++) {
        const float inv = 1.0f / lrow[rp + i];
        float* op = out + (size_t)(b * SEQ + qb * BQ + rp + i) * OUTD + DIMS + cp;
        float4 r0, r1;
        r0.x = o[i][0] * inv; r0.y = o[i][1] * inv;
        r0.z = o[i][2] * inv; r0.w = o[i][3] * inv;
        r1.x = o[i][4] * inv; r1.y = o[i][5] * inv;
        r1.z = o[i][6] * inv; r1.w = o[i][7] * inv;
        *(float4*)op       = r0;
        *(float4*)(op + 4) = r1;
    }
}

// ---------------------------------------------------------------------------
// Launch
// ---------------------------------------------------------------------------
extern "C" void kernel_launch(void* const* d_in, const int* in_sizes, int n_in,
                              void* d_out, int out_size) {
    const float* x   = (const float*)d_in[0];
    const float* Wk  = (const float*)d_in[1];
    const float* bk  = (const float*)d_in[2];
    const float* Wv  = (const float*)d_in[3];
    const float* bv  = (const float*)d_in[4];
    float* out = (float*)d_out;

    // 1) copy minibatch into out[:, :, :1024]
    copy_x_kernel<<<592, 256>>>(x, out);

    // 2) projections (keys & values)
    proj_kernel<<<dim3(NROWS / 128, 2), 256>>>(x, Wk, bk, Wv, bv);

    // 3) causal attention (heavy-diagonal CTAs first)
    cudaFuncSetAttribute(attn_kernel, cudaFuncAttributeMaxDynamicSharedMemorySize,
                         SMEM_BYTES);
    attn_kernel<<<BATCH * (SEQ / BQ), 256, SMEM_BYTES>>>(out);
}

// round 6
// speedup vs baseline: 2.1430x; 2.1430x over previous
#include <cuda_runtime.h>
#include <math.h>
#include <stdint.h>

// Problem constants
#define BATCH   8
#define SEQ     2048
#define DIMS    1024
#define KV      128
#define OUTD    1152
#define NROWS   (BATCH*SEQ)
#define SCALE   0.08838834764831845f

// Attention tiling
#define BQ      64
#define BK      64
#define HD      128

__device__ float g_keys[NROWS * KV];
__device__ float g_vals[NROWS * KV];

// ---------------------------------------------------------------------------
// helpers: tf32 convert + m16n8k8 tf32 mma
// ---------------------------------------------------------------------------
__device__ __forceinline__ uint32_t f2tf(float f) {
    uint32_t u;
    asm("cvt.rna.tf32.f32 %0, %1;" : "=r"(u) : "f"(f));
    return u;
}
__device__ __forceinline__ void mma8(float* c, const uint32_t* a, const uint32_t* b) {
    asm volatile(
        "mma.sync.aligned.m16n8k8.row.col.f32.tf32.tf32.f32 "
        "{%0,%1,%2,%3}, {%4,%5,%6,%7}, {%8,%9}, {%0,%1,%2,%3};"
        : "+f"(c[0]), "+f"(c[1]), "+f"(c[2]), "+f"(c[3])
        : "r"(a[0]), "r"(a[1]), "r"(a[2]), "r"(a[3]), "r"(b[0]), "r"(b[1]));
}

// ---------------------------------------------------------------------------
// Kernel 1: copy minibatch into out[:, :, 0:1024]
// ---------------------------------------------------------------------------
__global__ void copy_x_kernel(const float* __restrict__ x, float* __restrict__ out) {
    const int total4 = NROWS * (DIMS / 4);
    for (int idx = blockIdx.x * blockDim.x + threadIdx.x; idx < total4;
         idx += gridDim.x * blockDim.x) {
        int row = idx / (DIMS / 4);
        int c4  = idx % (DIMS / 4);
        float4 v = ((const float4*)x)[idx];
        *((float4*)(out + (size_t)row * OUTD) + c4) = v;
    }
}

// ---------------------------------------------------------------------------
// Kernel 2: projections via tf32 mma. CTA: 128 rows x 128 cols, k-chunk 32.
// 8 warps as 2(m) x 4(n): warp tile 64x32 (4 m-tiles x 4 n-tiles).
// blockIdx.y: 0 -> keys, 1 -> values
// ---------------------------------------------------------------------------
__global__ __launch_bounds__(256, 2)
void proj_tc_kernel(const float* __restrict__ x,
                    const float* __restrict__ Wkp, const float* __restrict__ bkp,
                    const float* __restrict__ Wvp, const float* __restrict__ bvp) {
    __shared__ uint32_t As[128][36];    // [m][k] tf32, stride 36 -> frag banks 4g+tig
    __shared__ uint32_t Ws[32][136];    // [k][n] tf32, stride 136 -> frag banks 8tig+g

    const float* W    = (blockIdx.y == 0) ? Wkp : Wvp;
    const float* bias = (blockIdx.y == 0) ? bkp : bvp;
    float*       outp = (blockIdx.y == 0) ? g_keys : g_vals;

    const int row0 = blockIdx.x * 128;
    const int tid  = threadIdx.x;
    const int wid  = tid >> 5;
    const int lane = tid & 31;
    const int g    = lane >> 2;
    const int tig  = lane & 3;
    const int wm   = (wid >> 2) * 64;   // warp m base (0 or 64)
    const int wn   = (wid & 3) * 32;    // warp n base

    // gmem load mappings
    const int am = tid >> 1;            // 0..127
    const int ak = (tid & 1) * 16;
    const int bkr = tid >> 3;           // 0..31
    const int bn  = (tid & 7) * 16;

    float acc[4][4][4];
    #pragma unroll
    for (int mt = 0; mt < 4; mt++)
        #pragma unroll
        for (int nt = 0; nt < 4; nt++)
            #pragma unroll
            for (int i = 0; i < 4; i++) acc[mt][nt][i] = 0.0f;

    for (int kc = 0; kc < DIMS; kc += 32) {
        // A tile: X[row0+am][kc+ak .. +15]
        {
            const float* xp = x + (size_t)(row0 + am) * DIMS + kc + ak;
            #pragma unroll
            for (int i = 0; i < 4; i++) {
                float4 v = *(const float4*)(xp + i * 4);
                uint4 t;
                t.x = f2tf(v.x); t.y = f2tf(v.y); t.z = f2tf(v.z); t.w = f2tf(v.w);
                *(uint4*)&As[am][ak + i * 4] = t;
            }
        }
        // W tile: W[kc+bkr][bn .. +15]
        {
            const float* wp = W + (size_t)(kc + bkr) * KV + bn;
            #pragma unroll
            for (int i = 0; i < 4; i++) {
                float4 v = *(const float4*)(wp + i * 4);
                uint4 t;
                t.x = f2tf(v.x); t.y = f2tf(v.y); t.z = f2tf(v.z); t.w = f2tf(v.w);
                *(uint4*)&Ws[bkr][bn + i * 4] = t;
            }
        }
        __syncthreads();

        #pragma unroll
        for (int ks = 0; ks < 4; ks++) {
            const int k0 = ks * 8;
            uint32_t b[4][2];
            #pragma unroll
            for (int nt = 0; nt < 4; nt++) {
                const int n = wn + nt * 8 + g;
                b[nt][0] = Ws[k0 + tig][n];
                b[nt][1] = Ws[k0 + tig + 4][n];
            }
            #pragma unroll
            for (int mt = 0; mt < 4; mt++) {
                const int m = wm + mt * 16;
                uint32_t a[4];
                a[0] = As[m + g][k0 + tig];
                a[1] = As[m + g + 8][k0 + tig];
                a[2] = As[m + g][k0 + tig + 4];
                a[3] = As[m + g + 8][k0 + tig + 4];
                #pragma unroll
                for (int nt = 0; nt < 4; nt++)
                    mma8(acc[mt][nt], a, b[nt]);
            }
        }
        __syncthreads();
    }

    // epilogue: add bias, store pairs
    #pragma unroll
    for (int nt = 0; nt < 4; nt++) {
        const int c0 = wn + nt * 8 + 2 * tig;
        const float b0 = bias[c0], b1 = bias[c0 + 1];
        #pragma unroll
        for (int mt = 0; mt < 4; mt++) {
            const int r0 = row0 + wm + mt * 16 + g;
            float2 lo = make_float2(acc[mt][nt][0] + b0, acc[mt][nt][1] + b1);
            float2 hi = make_float2(acc[mt][nt][2] + b0, acc[mt][nt][3] + b1);
            *(float2*)(outp + (size_t)r0 * KV + c0)       = lo;
            *(float2*)(outp + (size_t)(r0 + 8) * KV + c0) = hi;
        }
    }
}

// ---------------------------------------------------------------------------
// Kernel 3: causal flash attention via tf32 mma.
// CTA: 64 q-rows; 8 warps as 4(m) x 2(n).
// Q fragments register-resident (loaded once). smem: Ks/Vs/Ps + m/l/alpha.
// ---------------------------------------------------------------------------
#define KS_STRIDE 132   // banks: 4g+tig (conflict-free B-frag phase1)
#define VS_STRIDE 136   // banks: 8tig+g (conflict-free B-frag phase2)
#define PS_STRIDE 68    // banks: 4g+tig (conflict-free A-frag phase2)

#define SM_KS 0
#define SM_VS (SM_KS + 64*KS_STRIDE)
#define SM_PS (SM_VS + 64*VS_STRIDE)
#define SM_M  (SM_PS + 64*PS_STRIDE)
#define SM_L  (SM_M + 64)
#define SM_A  (SM_L + 64)
#define ATTN_SMEM_WORDS (SM_A + 64)
#define ATTN_SMEM_BYTES (ATTN_SMEM_WORDS * 4)

extern __shared__ uint32_t smw[];

__global__ __launch_bounds__(256, 1)
void attn_tc_kernel(float* __restrict__ out) {
    const int bid = blockIdx.x;
    const int b   = bid % BATCH;
    const int qb  = (SEQ / BQ - 1) - bid / BATCH;   // heavy blocks first

    uint32_t* Ks = smw + SM_KS;          // [64][KS_STRIDE]  (t, k)
    uint32_t* Vs = smw + SM_VS;          // [64][VS_STRIDE]  (t, d)
    uint32_t* Ps = smw + SM_PS;          // [64][PS_STRIDE]  (q, t)
    float* mrow  = (float*)(smw + SM_M);
    float* lrow  = (float*)(smw + SM_L);
    float* arow  = (float*)(smw + SM_A);

    const int tid  = threadIdx.x;
    const int wid  = tid >> 5;
    const int lane = tid & 31;
    const int g    = lane >> 2;
    const int tig  = lane & 3;
    const int mw   = wid >> 1;           // 0..3: q-row group (16 rows)
    const int nw   = wid & 1;            // 0..1: col group

    // ---- Q fragments: rows qb*64 + mw*16 .. +15, all 128 k. Register-resident.
    uint32_t aq[16][4];
    {
        const float* gq = g_keys + (size_t)(b * SEQ + qb * BQ + mw * 16) * KV;
        #pragma unroll
        for (int ks = 0; ks < 16; ks++) {
            const int k0 = ks * 8;
            aq[ks][0] = f2tf(gq[(size_t)g * KV + k0 + tig]);
            aq[ks][1] = f2tf(gq[(size_t)(g + 8) * KV + k0 + tig]);
            aq[ks][2] = f2tf(gq[(size_t)g * KV + k0 + tig + 4]);
            aq[ks][3] = f2tf(gq[(size_t)(g + 8) * KV + k0 + tig + 4]);
        }
    }
    if (tid < 64) { mrow[tid] = -1e30f; lrow[tid] = 0.0f; }

    float o[8][4];
    #pragma unroll
    for (int nt = 0; nt < 8; nt++)
        #pragma unroll
        for (int i = 0; i < 4; i++) o[nt][i] = 0.0f;

    // K/V gmem->smem mapping: r = tid/4, kq = (tid%4)*32
    const int ldr = tid >> 2;
    const int ldk = (tid & 3) * 32;

    for (int kb = 0; kb <= qb; kb++) {
        __syncthreads();   // previous phase2 done reading Ks/Vs/Ps

        // ---- load K/V tile (tf32-rounded) ----
        {
            const float* gk = g_keys + (size_t)(b * SEQ + kb * BK + ldr) * KV + ldk;
            const float* gv = g_vals + (size_t)(b * SEQ + kb * BK + ldr) * KV + ldk;
            #pragma unroll
            for (int i = 0; i < 32; i += 4) {
                float4 kv = *(const float4*)(gk + i);
                float4 vv = *(const float4*)(gv + i);
                uint4 kt, vt;
                kt.x = f2tf(kv.x); kt.y = f2tf(kv.y); kt.z = f2tf(kv.z); kt.w = f2tf(kv.w);
                vt.x = f2tf(vv.x); vt.y = f2tf(vv.y); vt.z = f2tf(vv.z); vt.w = f2tf(vv.w);
                *(uint4*)&Ks[ldr * KS_STRIDE + ldk + i] = kt;
                *(uint4*)&Vs[ldr * VS_STRIDE + ldk + i] = vt;
            }
        }
        __syncthreads();

        // ---- phase 1: S = Q @ K^T (warp tile 16x32 = 4 n-tiles) ----
        float sacc[4][4];
        #pragma unroll
        for (int nt = 0; nt < 4; nt++)
            #pragma unroll
            for (int i = 0; i < 4; i++) sacc[nt][i] = 0.0f;

        #pragma unroll
        for (int ks = 0; ks < 16; ks++) {
            const int k0 = ks * 8;
            uint32_t bfr[4][2];
            #pragma unroll
            for (int nt = 0; nt < 4; nt++) {
                const int tr = nw * 32 + nt * 8 + g;
                bfr[nt][0] = Ks[tr * KS_STRIDE + k0 + tig];
                bfr[nt][1] = Ks[tr * KS_STRIDE + k0 + tig + 4];
            }
            #pragma unroll
            for (int nt = 0; nt < 4; nt++)
                mma8(sacc[nt], aq[ks], bfr[nt]);
        }

        // mask + scale + write to Ps (as float bits)
        {
            const int qr_lo = qb * BQ + mw * 16 + g;
            const int qr_hi = qr_lo + 8;
            #pragma unroll
            for (int nt = 0; nt < 4; nt++) {
                const int tc = kb * BK + nw * 32 + nt * 8 + 2 * tig;
                float2 lo, hi;
                lo.x = (tc     > qr_lo) ? -1e30f : sacc[nt][0] * SCALE;
                lo.y = (tc + 1 > qr_lo) ? -1e30f : sacc[nt][1] * SCALE;
                hi.x = (tc     > qr_hi) ? -1e30f : sacc[nt][2] * SCALE;
                hi.y = (tc + 1 > qr_hi) ? -1e30f : sacc[nt][3] * SCALE;
                const int pc = nw * 32 + nt * 8 + 2 * tig;
                *(float2*)&Ps[(mw * 16 + g) * PS_STRIDE + pc]     = lo;
                *(float2*)&Ps[(mw * 16 + g + 8) * PS_STRIDE + pc] = hi;
            }
        }
        __syncthreads();

        // ---- online softmax (4 threads per row, 16 cols each) ----
        {
            const int r    = tid >> 2;
            const int part = tid & 3;
            float* prow = (float*)&Ps[r * PS_STRIDE + part * 16];
            float tmax = -1e30f;
            #pragma unroll
            for (int j = 0; j < 16; j++) tmax = fmaxf(tmax, prow[j]);
            tmax = fmaxf(tmax, __shfl_xor_sync(0xffffffffu, tmax, 1));
            tmax = fmaxf(tmax, __shfl_xor_sync(0xffffffffu, tmax, 2));
            const float mold = mrow[r];
            const float mnew = fmaxf(mold, tmax);
            const float al   = __expf(mold - mnew);
            float sum = 0.0f;
            #pragma unroll
            for (int j = 0; j < 16; j++) {
                float p = __expf(prow[j] - mnew);
                uint32_t pb = f2tf(p);             // round P to tf32 (what PV consumes)
                ((uint32_t*)prow)[j] = pb;
                sum += __uint_as_float(pb);
            }
            sum += __shfl_xor_sync(0xffffffffu, sum, 1);
            sum += __shfl_xor_sync(0xffffffffu, sum, 2);
            if (part == 0) {
                mrow[r] = mnew;
                lrow[r] = lrow[r] * al + sum;
                arow[r] = al;
            }
        }
        __syncthreads();

        // ---- phase 2: O = O*alpha + P @ V (warp tile 16x64 = 8 n-tiles) ----
        {
            const float a_lo = arow[mw * 16 + g];
            const float a_hi = arow[mw * 16 + g + 8];
            #pragma unroll
            for (int nt = 0; nt < 8; nt++) {
                o[nt][0] *= a_lo; o[nt][1] *= a_lo;
                o[nt][2] *= a_hi; o[nt][3] *= a_hi;
            }
            #pragma unroll
            for (int ks = 0; ks < 8; ks++) {
                const int k0 = ks * 8;
                uint32_t ap[4];
                ap[0] = Ps[(mw * 16 + g) * PS_STRIDE + k0 + tig];
                ap[1] = Ps[(mw * 16 + g + 8) * PS_STRIDE + k0 + tig];
                ap[2] = Ps[(mw * 16 + g) * PS_STRIDE + k0 + tig + 4];
                ap[3] = Ps[(mw * 16 + g + 8) * PS_STRIDE + k0 + tig + 4];
                #pragma unroll
                for (int nt = 0; nt < 8; nt++) {
                    const int d = nw * 64 + nt * 8 + g;
                    uint32_t bv[2];
                    bv[0] = Vs[(k0 + tig) * VS_STRIDE + d];
                    bv[1] = Vs[(k0 + tig + 4) * VS_STRIDE + d];
                    mma8(o[nt], ap, bv);
                }
            }
        }
    }

    // ---- epilogue: normalize, store ----
    {
        const int r_lo = mw * 16 + g;
        const int r_hi = r_lo + 8;
        const float inv_lo = 1.0f / lrow[r_lo];
        const float inv_hi = 1.0f / lrow[r_hi];
        float* op_lo = out + (size_t)(b * SEQ + qb * BQ + r_lo) * OUTD + DIMS;
        float* op_hi = out + (size_t)(b * SEQ + qb * BQ + r_hi) * OUTD + DIMS;
        #pragma unroll
        for (int nt = 0; nt < 8; nt++) {
            const int d = nw * 64 + nt * 8 + 2 * tig;
            *(float2*)(op_lo + d) = make_float2(o[nt][0] * inv_lo, o[nt][1] * inv_lo);
            *(float2*)(op_hi + d) = make_float2(o[nt][2] * inv_hi, o[nt][3] * inv_hi);
        }
    }
}

// ---------------------------------------------------------------------------
// Launch
// ---------------------------------------------------------------------------
extern "C" void kernel_launch(void* const* d_in, const int* in_sizes, int n_in,
                              void* d_out, int out_size) {
    const float* x   = (const float*)d_in[0];
    const float* Wk  = (const float*)d_in[1];
    const float* bk  = (const float*)d_in[2];
    const float* Wv  = (const float*)d_in[3];
    const float* bv  = (const float*)d_in[4];
    float* out = (float*)d_out;

    copy_x_kernel<<<592, 256>>>(x, out);
    proj_tc_kernel<<<dim3(NROWS / 128, 2), 256>>>(x, Wk, bk, Wv, bv);

    cudaFuncSetAttribute(attn_tc_kernel, cudaFuncAttributeMaxDynamicSharedMemorySize,
                         ATTN_SMEM_BYTES);
    attn_tc_kernel<<<BATCH * (SEQ / BQ), 256, ATTN_SMEM_BYTES>>>(out);
}

// round 7
// speedup vs baseline: 2.5755x; 1.2018x over previous
#include <cuda_runtime.h>
#include <math.h>
#include <stdint.h>

// Problem constants
#define BATCH   8
#define SEQ     2048
#define DIMS    1024
#define KV      128
#define OUTD    1152
#define NROWS   (BATCH*SEQ)
#define SCALE   0.08838834764831845f

// Attention tiling
#define BQ      64
#define BK      64
#define HD      128

__device__ float g_keys[NROWS * KV];
__device__ float g_vals[NROWS * KV];

// ---------------------------------------------------------------------------
// helpers: tf32 convert + m16n8k8 tf32 mma + cp.async
// ---------------------------------------------------------------------------
__device__ __forceinline__ uint32_t f2tf(float f) {
    uint32_t u;
    asm("cvt.rna.tf32.f32 %0, %1;" : "=r"(u) : "f"(f));
    return u;
}
__device__ __forceinline__ void mma8(float* c, const uint32_t* a, const uint32_t* b) {
    asm volatile(
        "mma.sync.aligned.m16n8k8.row.col.f32.tf32.tf32.f32 "
        "{%0,%1,%2,%3}, {%4,%5,%6,%7}, {%8,%9}, {%0,%1,%2,%3};"
        : "+f"(c[0]), "+f"(c[1]), "+f"(c[2]), "+f"(c[3])
        : "r"(a[0]), "r"(a[1]), "r"(a[2]), "r"(a[3]), "r"(b[0]), "r"(b[1]));
}
__device__ __forceinline__ void cp16(uint32_t smem_addr, const void* gptr) {
    asm volatile("cp.async.cg.shared.global [%0], [%1], 16;"
                 :: "r"(smem_addr), "l"(gptr));
}
__device__ __forceinline__ void cp_commit() {
    asm volatile("cp.async.commit_group;");
}

// ---------------------------------------------------------------------------
// Kernel 1: projections via tf32 mma + fused X-copy into out[:, :, :1024].
// CTA: 128 rows x 128 cols, k-chunk 32. 8 warps as 2(m) x 4(n).
// blockIdx.y: 0 -> keys (also copies X slice to out), 1 -> values
// ---------------------------------------------------------------------------
__global__ __launch_bounds__(256, 2)
void proj_tc_kernel(const float* __restrict__ x,
                    const float* __restrict__ Wkp, const float* __restrict__ bkp,
                    const float* __restrict__ Wvp, const float* __restrict__ bvp,
                    float* __restrict__ out) {
    __shared__ uint32_t As[128][36];    // [m][k] tf32, stride 36 -> frag banks 4g+tig
    __shared__ uint32_t Ws[32][136];    // [k][n] tf32, stride 136 -> frag banks 8tig+g

    const float* W    = (blockIdx.y == 0) ? Wkp : Wvp;
    const float* bias = (blockIdx.y == 0) ? bkp : bvp;
    float*       outp = (blockIdx.y == 0) ? g_keys : g_vals;

    const int row0 = blockIdx.x * 128;
    const int tid  = threadIdx.x;
    const int wid  = tid >> 5;
    const int lane = tid & 31;
    const int g    = lane >> 2;
    const int tig  = lane & 3;
    const int wm   = (wid >> 2) * 64;   // warp m base (0 or 64)
    const int wn   = (wid & 3) * 32;    // warp n base

    // gmem load mappings
    const int am = tid >> 1;            // 0..127
    const int ak = (tid & 1) * 16;
    const int bkr = tid >> 3;           // 0..31
    const int bn  = (tid & 7) * 16;

    float acc[4][4][4];
    #pragma unroll
    for (int mt = 0; mt < 4; mt++)
        #pragma unroll
        for (int nt = 0; nt < 4; nt++)
            #pragma unroll
            for (int i = 0; i < 4; i++) acc[mt][nt][i] = 0.0f;

    for (int kc = 0; kc < DIMS; kc += 32) {
        // A tile: X[row0+am][kc+ak .. +15] ; y==0 also copies slice into out
        {
            const float* xp = x + (size_t)(row0 + am) * DIMS + kc + ak;
            float* op = out + (size_t)(row0 + am) * OUTD + kc + ak;
            #pragma unroll
            for (int i = 0; i < 4; i++) {
                float4 v = *(const float4*)(xp + i * 4);
                if (blockIdx.y == 0) *(float4*)(op + i * 4) = v;
                uint4 t;
                t.x = f2tf(v.x); t.y = f2tf(v.y); t.z = f2tf(v.z); t.w = f2tf(v.w);
                *(uint4*)&As[am][ak + i * 4] = t;
            }
        }
        // W tile: W[kc+bkr][bn .. +15]
        {
            const float* wp = W + (size_t)(kc + bkr) * KV + bn;
            #pragma unroll
            for (int i = 0; i < 4; i++) {
                float4 v = *(const float4*)(wp + i * 4);
                uint4 t;
                t.x = f2tf(v.x); t.y = f2tf(v.y); t.z = f2tf(v.z); t.w = f2tf(v.w);
                *(uint4*)&Ws[bkr][bn + i * 4] = t;
            }
        }
        __syncthreads();

        #pragma unroll
        for (int ks = 0; ks < 4; ks++) {
            const int k0 = ks * 8;
            uint32_t b[4][2];
            #pragma unroll
            for (int nt = 0; nt < 4; nt++) {
                const int n = wn + nt * 8 + g;
                b[nt][0] = Ws[k0 + tig][n];
                b[nt][1] = Ws[k0 + tig + 4][n];
            }
            #pragma unroll
            for (int mt = 0; mt < 4; mt++) {
                const int m = wm + mt * 16;
                uint32_t a[4];
                a[0] = As[m + g][k0 + tig];
                a[1] = As[m + g + 8][k0 + tig];
                a[2] = As[m + g][k0 + tig + 4];
                a[3] = As[m + g + 8][k0 + tig + 4];
                #pragma unroll
                for (int nt = 0; nt < 4; nt++)
                    mma8(acc[mt][nt], a, b[nt]);
            }
        }
        __syncthreads();
    }

    // epilogue: add bias, store pairs
    #pragma unroll
    for (int nt = 0; nt < 4; nt++) {
        const int c0 = wn + nt * 8 + 2 * tig;
        const float b0 = bias[c0], b1 = bias[c0 + 1];
        #pragma unroll
        for (int mt = 0; mt < 4; mt++) {
            const int r0 = row0 + wm + mt * 16 + g;
            float2 lo = make_float2(acc[mt][nt][0] + b0, acc[mt][nt][1] + b1);
            float2 hi = make_float2(acc[mt][nt][2] + b0, acc[mt][nt][3] + b1);
            *(float2*)(outp + (size_t)r0 * KV + c0)       = lo;
            *(float2*)(outp + (size_t)(r0 + 8) * KV + c0) = hi;
        }
    }
}

// ---------------------------------------------------------------------------
// Kernel 2: causal flash attention via tf32 mma, cp.async double-buffered K/V.
// CTA: 64 q-rows; 8 warps as 4(m) x 2(n). Q fragments register-resident.
// K/V stored raw fp32 in smem; mma truncates to tf32 (rel_err budget checked).
// ---------------------------------------------------------------------------
#define KS_STRIDE 132   // banks: 4g+tig (conflict-free B-frag phase1)
#define VS_STRIDE 136   // banks: 8tig+g (conflict-free B-frag phase2)
#define PS_STRIDE 68    // banks: 4g+tig (conflict-free A-frag phase2)

#define KS_WORDS (64*KS_STRIDE)
#define VS_WORDS (64*VS_STRIDE)

#define SM_KS 0                         // 2 buffers
#define SM_VS (SM_KS + 2*KS_WORDS)      // 2 buffers
#define SM_PS (SM_VS + 2*VS_WORDS)
#define SM_M  (SM_PS + 64*PS_STRIDE)
#define SM_L  (SM_M + 64)
#define SM_A  (SM_L + 64)
#define ATTN_SMEM_WORDS (SM_A + 64)
#define ATTN_SMEM_BYTES (ATTN_SMEM_WORDS * 4)

extern __shared__ uint32_t smw[];

__global__ __launch_bounds__(256, 1)
void attn_tc_kernel(float* __restrict__ out) {
    const int bid = blockIdx.x;
    const int b   = bid % BATCH;
    const int qb  = (SEQ / BQ - 1) - bid / BATCH;   // heavy blocks first

    uint32_t* Ps = smw + SM_PS;          // [64][PS_STRIDE]  (q, t)
    float* mrow  = (float*)(smw + SM_M);
    float* lrow  = (float*)(smw + SM_L);
    float* arow  = (float*)(smw + SM_A);

    const int tid  = threadIdx.x;
    const int wid  = tid >> 5;
    const int lane = tid & 31;
    const int g    = lane >> 2;
    const int tig  = lane & 3;
    const int mw   = wid >> 1;           // 0..3: q-row group (16 rows)
    const int nw   = wid & 1;            // 0..1: col group

    // K/V gmem->smem mapping: r = tid/4, k0 = (tid%4)*32  (8x 16B cp.async)
    const int ldr = tid >> 2;
    const int ldk = (tid & 3) * 32;
    const float* gkb = g_keys + (size_t)(b * SEQ + ldr) * KV + ldk;
    const float* gvb = g_vals + (size_t)(b * SEQ + ldr) * KV + ldk;
    const uint32_t ks_base = (uint32_t)__cvta_generic_to_shared(smw + SM_KS)
                           + (uint32_t)(ldr * KS_STRIDE + ldk) * 4u;
    const uint32_t vs_base = (uint32_t)__cvta_generic_to_shared(smw + SM_VS)
                           + (uint32_t)(ldr * VS_STRIDE + ldk) * 4u;

    // ---- prefetch tile 0 into buffer 0 ----
    {
        const float* gk = gkb;           // kb=0
        const float* gv = gvb;
        #pragma unroll
        for (int i = 0; i < 32; i += 4) {
            cp16(ks_base + i * 4u, gk + i);
            cp16(vs_base + i * 4u, gv + i);
        }
        cp_commit();
    }

    // ---- Q fragments: rows qb*64 + mw*16 .. +15, all 128 k. Register-resident.
    uint32_t aq[16][4];
    {
        const float* gq = g_keys + (size_t)(b * SEQ + qb * BQ + mw * 16) * KV;
        #pragma unroll
        for (int ks = 0; ks < 16; ks++) {
            const int k0 = ks * 8;
            aq[ks][0] = f2tf(gq[(size_t)g * KV + k0 + tig]);
            aq[ks][1] = f2tf(gq[(size_t)(g + 8) * KV + k0 + tig]);
            aq[ks][2] = f2tf(gq[(size_t)g * KV + k0 + tig + 4]);
            aq[ks][3] = f2tf(gq[(size_t)(g + 8) * KV + k0 + tig + 4]);
        }
    }
    if (tid < 64) { mrow[tid] = -1e30f; lrow[tid] = 0.0f; }

    float o[8][4];
    #pragma unroll
    for (int nt = 0; nt < 8; nt++)
        #pragma unroll
        for (int i = 0; i < 4; i++) o[nt][i] = 0.0f;

    for (int kb = 0; kb <= qb; kb++) {
        const int cur = kb & 1;
        uint32_t* Ks = smw + SM_KS + cur * KS_WORDS;
        uint32_t* Vs = smw + SM_VS + cur * VS_WORDS;

        __syncthreads();   // prev phase2 done reading Ps and buf cur^1

        // ---- prefetch next tile into buffer cur^1, wait for tile kb ----
        if (kb < qb) {
            const uint32_t koff = (uint32_t)((cur ^ 1) * KS_WORDS) * 4u;
            const uint32_t voff = (uint32_t)((cur ^ 1) * VS_WORDS) * 4u;
            const float* gk = gkb + (size_t)(kb + 1) * BK * KV;
            const float* gv = gvb + (size_t)(kb + 1) * BK * KV;
            #pragma unroll
            for (int i = 0; i < 32; i += 4) {
                cp16(ks_base + koff + i * 4u, gk + i);
                cp16(vs_base + voff + i * 4u, gv + i);
            }
            cp_commit();
            asm volatile("cp.async.wait_group 1;");
        } else {
            asm volatile("cp.async.wait_group 0;");
        }
        __syncthreads();   // tile kb visible to all threads

        // ---- phase 1: S = Q @ K^T (warp tile 16x32 = 4 n-tiles) ----
        float sacc[4][4];
        #pragma unroll
        for (int nt = 0; nt < 4; nt++)
            #pragma unroll
            for (int i = 0; i < 4; i++) sacc[nt][i] = 0.0f;

        #pragma unroll
        for (int ks = 0; ks < 16; ks++) {
            const int k0 = ks * 8;
            uint32_t bfr[4][2];
            #pragma unroll
            for (int nt = 0; nt < 4; nt++) {
                const int tr = nw * 32 + nt * 8 + g;
                bfr[nt][0] = Ks[tr * KS_STRIDE + k0 + tig];
                bfr[nt][1] = Ks[tr * KS_STRIDE + k0 + tig + 4];
            }
            #pragma unroll
            for (int nt = 0; nt < 4; nt++)
                mma8(sacc[nt], aq[ks], bfr[nt]);
        }

        // mask + scale + write to Ps (as float bits)
        {
            const int qr_lo = qb * BQ + mw * 16 + g;
            const int qr_hi = qr_lo + 8;
            #pragma unroll
            for (int nt = 0; nt < 4; nt++) {
                const int tc = kb * BK + nw * 32 + nt * 8 + 2 * tig;
                float2 lo, hi;
                lo.x = (tc     > qr_lo) ? -1e30f : sacc[nt][0] * SCALE;
                lo.y = (tc + 1 > qr_lo) ? -1e30f : sacc[nt][1] * SCALE;
                hi.x = (tc     > qr_hi) ? -1e30f : sacc[nt][2] * SCALE;
                hi.y = (tc + 1 > qr_hi) ? -1e30f : sacc[nt][3] * SCALE;
                const int pc = nw * 32 + nt * 8 + 2 * tig;
                *(float2*)&Ps[(mw * 16 + g) * PS_STRIDE + pc]     = lo;
                *(float2*)&Ps[(mw * 16 + g + 8) * PS_STRIDE + pc] = hi;
            }
        }
        __syncthreads();

        // ---- online softmax (4 threads per row, 16 cols each) ----
        {
            const int r    = tid >> 2;
            const int part = tid & 3;
            float* prow = (float*)&Ps[r * PS_STRIDE + part * 16];
            float tmax = -1e30f;
            #pragma unroll
            for (int j = 0; j < 16; j++) tmax = fmaxf(tmax, prow[j]);
            tmax = fmaxf(tmax, __shfl_xor_sync(0xffffffffu, tmax, 1));
            tmax = fmaxf(tmax, __shfl_xor_sync(0xffffffffu, tmax, 2));
            const float mold = mrow[r];
            const float mnew = fmaxf(mold, tmax);
            const float al   = __expf(mold - mnew);
            float sum = 0.0f;
            #pragma unroll
            for (int j = 0; j < 16; j++) {
                float p = __expf(prow[j] - mnew);
                uint32_t pb = f2tf(p);             // round P to tf32 (what PV consumes)
                ((uint32_t*)prow)[j] = pb;
                sum += __uint_as_float(pb);
            }
            sum += __shfl_xor_sync(0xffffffffu, sum, 1);
            sum += __shfl_xor_sync(0xffffffffu, sum, 2);
            if (part == 0) {
                mrow[r] = mnew;
                lrow[r] = lrow[r] * al + sum;
                arow[r] = al;
            }
        }
        __syncthreads();

        // ---- phase 2: O = O*alpha + P @ V (warp tile 16x64 = 8 n-tiles) ----
        {
            const float a_lo = arow[mw * 16 + g];
            const float a_hi = arow[mw * 16 + g + 8];
            #pragma unroll
            for (int nt = 0; nt < 8; nt++) {
                o[nt][0] *= a_lo; o[nt][1] *= a_lo;
                o[nt][2] *= a_hi; o[nt][3] *= a_hi;
            }
            #pragma unroll
            for (int ks = 0; ks < 8; ks++) {
                const int k0 = ks * 8;
                uint32_t ap[4];
                ap[0] = Ps[(mw * 16 + g) * PS_STRIDE + k0 + tig];
                ap[1] = Ps[(mw * 16 + g + 8) * PS_STRIDE + k0 + tig];
                ap[2] = Ps[(mw * 16 + g) * PS_STRIDE + k0 + tig + 4];
                ap[3] = Ps[(mw * 16 + g + 8) * PS_STRIDE + k0 + tig + 4];
                #pragma unroll
                for (int nt = 0; nt < 8; nt++) {
                    const int d = nw * 64 + nt * 8 + g;
                    uint32_t bv[2];
                    bv[0] = Vs[(k0 + tig) * VS_STRIDE + d];
                    bv[1] = Vs[(k0 + tig + 4) * VS_STRIDE + d];
                    mma8(o[nt], ap, bv);
                }
            }
        }
    }

    // ---- epilogue: normalize, store ----
    {
        const int r_lo = mw * 16 + g;
        const int r_hi = r_lo + 8;
        const float inv_lo = 1.0f / lrow[r_lo];
        const float inv_hi = 1.0f / lrow[r_hi];
        float* op_lo = out + (size_t)(b * SEQ + qb * BQ + r_lo) * OUTD + DIMS;
        float* op_hi = out + (size_t)(b * SEQ + qb * BQ + r_hi) * OUTD + DIMS;
        #pragma unroll
        for (int nt = 0; nt < 8; nt++) {
            const int d = nw * 64 + nt * 8 + 2 * tig;
            *(float2*)(op_lo + d) = make_float2(o[nt][0] * inv_lo, o[nt][1] * inv_lo);
            *(float2*)(op_hi + d) = make_float2(o[nt][2] * inv_hi, o[nt][3] * inv_hi);
        }
    }
}

// ---------------------------------------------------------------------------
// Launch
// ---------------------------------------------------------------------------
extern "C" void kernel_launch(void* const* d_in, const int* in_sizes, int n_in,
                              void* d_out, int out_size) {
    const float* x   = (const float*)d_in[0];
    const float* Wk  = (const float*)d_in[1];
    const float* bk  = (const float*)d_in[2];
    const float* Wv  = (const float*)d_in[3];
    const float* bv  = (const float*)d_in[4];
    float* out = (float*)d_out;

    proj_tc_kernel<<<dim3(NROWS / 128, 2), 256>>>(x, Wk, bk, Wv, bv, out);

    cudaFuncSetAttribute(attn_tc_kernel, cudaFuncAttributeMaxDynamicSharedMemorySize,
                         ATTN_SMEM_BYTES);
    attn_tc_kernel<<<BATCH * (SEQ / BQ), 256, ATTN_SMEM_BYTES>>>(out);
}

// round 8
// speedup vs baseline: 2.6913x; 1.0449x over previous
#include <cuda_runtime.h>
#include <math.h>
#include <stdint.h>

// Problem constants
#define BATCH   8
#define SEQ     2048
#define DIMS    1024
#define KV      128
#define OUTD    1152
#define NROWS   (BATCH*SEQ)
#define SCALE   0.08838834764831845f

// Attention tiling
#define BQ      64
#define BK      64
#define HD      128

__device__ float g_keys[NROWS * KV];
__device__ float g_vals[NROWS * KV];

// ---------------------------------------------------------------------------
// helpers: tf32 convert + m16n8k8 tf32 mma + cp.async
// ---------------------------------------------------------------------------
__device__ __forceinline__ uint32_t f2tf(float f) {
    uint32_t u;
    asm("cvt.rna.tf32.f32 %0, %1;" : "=r"(u) : "f"(f));
    return u;
}
__device__ __forceinline__ void mma8(float* c, const uint32_t* a, const uint32_t* b) {
    asm volatile(
        "mma.sync.aligned.m16n8k8.row.col.f32.tf32.tf32.f32 "
        "{%0,%1,%2,%3}, {%4,%5,%6,%7}, {%8,%9}, {%0,%1,%2,%3};"
        : "+f"(c[0]), "+f"(c[1]), "+f"(c[2]), "+f"(c[3])
        : "r"(a[0]), "r"(a[1]), "r"(a[2]), "r"(a[3]), "r"(b[0]), "r"(b[1]));
}
__device__ __forceinline__ void cp16(uint32_t smem_addr, const void* gptr) {
    asm volatile("cp.async.cg.shared.global [%0], [%1], 16;"
                 :: "r"(smem_addr), "l"(gptr));
}
__device__ __forceinline__ void cp_commit() {
    asm volatile("cp.async.commit_group;");
}

// ---------------------------------------------------------------------------
// Kernel 1: projections via tf32 mma + fused X-copy into out[:, :, :1024].
// (unchanged this round — measure before touching)
// ---------------------------------------------------------------------------
__global__ __launch_bounds__(256, 2)
void proj_tc_kernel(const float* __restrict__ x,
                    const float* __restrict__ Wkp, const float* __restrict__ bkp,
                    const float* __restrict__ Wvp, const float* __restrict__ bvp,
                    float* __restrict__ out) {
    __shared__ uint32_t As[128][36];
    __shared__ uint32_t Ws[32][136];

    const float* W    = (blockIdx.y == 0) ? Wkp : Wvp;
    const float* bias = (blockIdx.y == 0) ? bkp : bvp;
    float*       outp = (blockIdx.y == 0) ? g_keys : g_vals;

    const int row0 = blockIdx.x * 128;
    const int tid  = threadIdx.x;
    const int wid  = tid >> 5;
    const int lane = tid & 31;
    const int g    = lane >> 2;
    const int tig  = lane & 3;
    const int wm   = (wid >> 2) * 64;
    const int wn   = (wid & 3) * 32;

    const int am = tid >> 1;
    const int ak = (tid & 1) * 16;
    const int bkr = tid >> 3;
    const int bn  = (tid & 7) * 16;

    float acc[4][4][4];
    #pragma unroll
    for (int mt = 0; mt < 4; mt++)
        #pragma unroll
        for (int nt = 0; nt < 4; nt++)
            #pragma unroll
            for (int i = 0; i < 4; i++) acc[mt][nt][i] = 0.0f;

    for (int kc = 0; kc < DIMS; kc += 32) {
        {
            const float* xp = x + (size_t)(row0 + am) * DIMS + kc + ak;
            float* op = out + (size_t)(row0 + am) * OUTD + kc + ak;
            #pragma unroll
            for (int i = 0; i < 4; i++) {
                float4 v = *(const float4*)(xp + i * 4);
                if (blockIdx.y == 0) *(float4*)(op + i * 4) = v;
                uint4 t;
                t.x = f2tf(v.x); t.y = f2tf(v.y); t.z = f2tf(v.z); t.w = f2tf(v.w);
                *(uint4*)&As[am][ak + i * 4] = t;
            }
        }
        {
            const float* wp = W + (size_t)(kc + bkr) * KV + bn;
            #pragma unroll
            for (int i = 0; i < 4; i++) {
                float4 v = *(const float4*)(wp + i * 4);
                uint4 t;
                t.x = f2tf(v.x); t.y = f2tf(v.y); t.z = f2tf(v.z); t.w = f2tf(v.w);
                *(uint4*)&Ws[bkr][bn + i * 4] = t;
            }
        }
        __syncthreads();

        #pragma unroll
        for (int ks = 0; ks < 4; ks++) {
            const int k0 = ks * 8;
            uint32_t b[4][2];
            #pragma unroll
            for (int nt = 0; nt < 4; nt++) {
                const int n = wn + nt * 8 + g;
                b[nt][0] = Ws[k0 + tig][n];
                b[nt][1] = Ws[k0 + tig + 4][n];
            }
            #pragma unroll
            for (int mt = 0; mt < 4; mt++) {
                const int m = wm + mt * 16;
                uint32_t a[4];
                a[0] = As[m + g][k0 + tig];
                a[1] = As[m + g + 8][k0 + tig];
                a[2] = As[m + g][k0 + tig + 4];
                a[3] = As[m + g + 8][k0 + tig + 4];
                #pragma unroll
                for (int nt = 0; nt < 4; nt++)
                    mma8(acc[mt][nt], a, b[nt]);
            }
        }
        __syncthreads();
    }

    #pragma unroll
    for (int nt = 0; nt < 4; nt++) {
        const int c0 = wn + nt * 8 + 2 * tig;
        const float b0 = bias[c0], b1 = bias[c0 + 1];
        #pragma unroll
        for (int mt = 0; mt < 4; mt++) {
            const int r0 = row0 + wm + mt * 16 + g;
            float2 lo = make_float2(acc[mt][nt][0] + b0, acc[mt][nt][1] + b1);
            float2 hi = make_float2(acc[mt][nt][2] + b0, acc[mt][nt][3] + b1);
            *(float2*)(outp + (size_t)r0 * KV + c0)       = lo;
            *(float2*)(outp + (size_t)(r0 + 8) * KV + c0) = hi;
        }
    }
}

// ---------------------------------------------------------------------------
// Kernel 2: FA2-style causal flash attention, tf32 mma, cp.async double-buffer.
// 128 threads = 4 warps; each warp owns 16 q-rows end-to-end:
//   full-width S (16x64), register softmax (quad shfl), per-warp P strip in
//   smem (syncwarp only), full-width PV (16x128), m/l/alpha in registers.
// Only 2 block barriers per tile-step (K/V ring protection).
// ---------------------------------------------------------------------------
#define KS_STRIDE 132   // banks: 4g+tig conflict-free B-frag (phase1)
#define VS_STRIDE 136   // banks: 8tig+g conflict-free B-frag (phase2)
#define PW_STRIDE 68    // banks: 4g+tig conflict-free A-frag (phase2)

#define KS_WORDS (64*KS_STRIDE)
#define VS_WORDS (64*VS_STRIDE)

#define SM_KS 0                         // 2 buffers
#define SM_VS (SM_KS + 2*KS_WORDS)      // 2 buffers
#define SM_PW (SM_VS + 2*VS_WORDS)      // 4 warps x 16 rows x PW_STRIDE
#define ATTN_SMEM_WORDS (SM_PW + 4*16*PW_STRIDE)
#define ATTN_SMEM_BYTES (ATTN_SMEM_WORDS * 4)

extern __shared__ uint32_t smw[];

__global__ __launch_bounds__(128, 1)
void attn_tc_kernel(float* __restrict__ out) {
    const int bid = blockIdx.x;
    const int b   = bid % BATCH;
    const int qb  = (SEQ / BQ - 1) - bid / BATCH;   // heavy blocks first

    const int tid  = threadIdx.x;
    const int wid  = tid >> 5;
    const int lane = tid & 31;
    const int g    = lane >> 2;
    const int tig  = lane & 3;

    uint32_t* Pw = smw + SM_PW + wid * 16 * PW_STRIDE;   // per-warp strip

    // K/V gmem->smem mapping: r = tid/2 (0..63), k0 = (tid&1)*64  (16x 16B each)
    const int ldr = tid >> 1;
    const int ldk = (tid & 1) * 64;
    const float* gkb = g_keys + (size_t)(b * SEQ + ldr) * KV + ldk;
    const float* gvb = g_vals + (size_t)(b * SEQ + ldr) * KV + ldk;
    const uint32_t ks_base = (uint32_t)__cvta_generic_to_shared(smw + SM_KS)
                           + (uint32_t)(ldr * KS_STRIDE + ldk) * 4u;
    const uint32_t vs_base = (uint32_t)__cvta_generic_to_shared(smw + SM_VS)
                           + (uint32_t)(ldr * VS_STRIDE + ldk) * 4u;

    // ---- prefetch tile 0 into buffer 0 ----
    {
        #pragma unroll
        for (int i = 0; i < 64; i += 4) {
            cp16(ks_base + i * 4u, gkb + i);
            cp16(vs_base + i * 4u, gvb + i);
        }
        cp_commit();
    }

    // ---- Q fragments: rows qb*64 + wid*16 .. +15, all 128 k. Register-resident.
    uint32_t aq[16][4];
    {
        const float* gq = g_keys + (size_t)(b * SEQ + qb * BQ + wid * 16) * KV;
        #pragma unroll
        for (int ks = 0; ks < 16; ks++) {
            const int k0 = ks * 8;
            aq[ks][0] = f2tf(gq[(size_t)g * KV + k0 + tig]);
            aq[ks][1] = f2tf(gq[(size_t)(g + 8) * KV + k0 + tig]);
            aq[ks][2] = f2tf(gq[(size_t)g * KV + k0 + tig + 4]);
            aq[ks][3] = f2tf(gq[(size_t)(g + 8) * KV + k0 + tig + 4]);
        }
    }

    // running stats (replicated across each quad)
    float m_lo = -1e30f, m_hi = -1e30f, l_lo = 0.0f, l_hi = 0.0f;

    float o[16][4];
    #pragma unroll
    for (int nt = 0; nt < 16; nt++)
        #pragma unroll
        for (int i = 0; i < 4; i++) o[nt][i] = 0.0f;

    for (int kb = 0; kb <= qb; kb++) {
        const int cur = kb & 1;
        const uint32_t* Ks = smw + SM_KS + cur * KS_WORDS;
        const uint32_t* Vs = smw + SM_VS + cur * VS_WORDS;

        __syncthreads();   // all warps done reading buffer cur (prev round)

        // ---- prefetch next tile into buffer cur^1, wait for tile kb ----
        if (kb < qb) {
            const uint32_t koff = (uint32_t)((cur ^ 1) * KS_WORDS) * 4u;
            const uint32_t voff = (uint32_t)((cur ^ 1) * VS_WORDS) * 4u;
            const float* gk = gkb + (size_t)(kb + 1) * BK * KV;
            const float* gv = gvb + (size_t)(kb + 1) * BK * KV;
            #pragma unroll
            for (int i = 0; i < 64; i += 4) {
                cp16(ks_base + koff + i * 4u, gk + i);
                cp16(vs_base + voff + i * 4u, gv + i);
            }
            cp_commit();
            asm volatile("cp.async.wait_group 1;");
        } else {
            asm volatile("cp.async.wait_group 0;");
        }
        __syncthreads();   // tile kb visible to all threads

        // ---- phase 1: S = Q @ K^T, full width (8 n-tiles of 8) ----
        float sacc[8][4];
        #pragma unroll
        for (int nt = 0; nt < 8; nt++)
            #pragma unroll
            for (int i = 0; i < 4; i++) sacc[nt][i] = 0.0f;

        #pragma unroll
        for (int ks = 0; ks < 16; ks++) {
            const int k0 = ks * 8;
            uint32_t bfr[8][2];
            #pragma unroll
            for (int nt = 0; nt < 8; nt++) {
                const int tr = nt * 8 + g;
                bfr[nt][0] = Ks[tr * KS_STRIDE + k0 + tig];
                bfr[nt][1] = Ks[tr * KS_STRIDE + k0 + tig + 4];
            }
            #pragma unroll
            for (int nt = 0; nt < 8; nt++)
                mma8(sacc[nt], aq[ks], bfr[nt]);
        }

        // ---- scale + causal mask (only diagonal tile needs it) ----
        const int r_lo = wid * 16 + g;       // row within 64 (kb==qb frame)
        const int r_hi = r_lo + 8;
        #pragma unroll
        for (int nt = 0; nt < 8; nt++) {
            const int c0 = nt * 8 + 2 * tig;
            if (kb == qb) {
                sacc[nt][0] = (c0     > r_lo) ? -1e30f : sacc[nt][0] * SCALE;
                sacc[nt][1] = (c0 + 1 > r_lo) ? -1e30f : sacc[nt][1] * SCALE;
                sacc[nt][2] = (c0     > r_hi) ? -1e30f : sacc[nt][2] * SCALE;
                sacc[nt][3] = (c0 + 1 > r_hi) ? -1e30f : sacc[nt][3] * SCALE;
            } else {
                sacc[nt][0] *= SCALE; sacc[nt][1] *= SCALE;
                sacc[nt][2] *= SCALE; sacc[nt][3] *= SCALE;
            }
        }

        // ---- register online softmax (quad shfl reductions) ----
        float tmax_lo = -1e30f, tmax_hi = -1e30f;
        #pragma unroll
        for (int nt = 0; nt < 8; nt++) {
            tmax_lo = fmaxf(tmax_lo, fmaxf(sacc[nt][0], sacc[nt][1]));
            tmax_hi = fmaxf(tmax_hi, fmaxf(sacc[nt][2], sacc[nt][3]));
        }
        tmax_lo = fmaxf(tmax_lo, __shfl_xor_sync(0xffffffffu, tmax_lo, 1));
        tmax_lo = fmaxf(tmax_lo, __shfl_xor_sync(0xffffffffu, tmax_lo, 2));
        tmax_hi = fmaxf(tmax_hi, __shfl_xor_sync(0xffffffffu, tmax_hi, 1));
        tmax_hi = fmaxf(tmax_hi, __shfl_xor_sync(0xffffffffu, tmax_hi, 2));

        const float mn_lo = fmaxf(m_lo, tmax_lo);
        const float mn_hi = fmaxf(m_hi, tmax_hi);
        const float al_lo = __expf(m_lo - mn_lo);
        const float al_hi = __expf(m_hi - mn_hi);
        m_lo = mn_lo; m_hi = mn_hi;

        float sum_lo = 0.0f, sum_hi = 0.0f;
        #pragma unroll
        for (int nt = 0; nt < 8; nt++) {
            uint32_t p0 = f2tf(__expf(sacc[nt][0] - mn_lo));
            uint32_t p1 = f2tf(__expf(sacc[nt][1] - mn_lo));
            uint32_t p2 = f2tf(__expf(sacc[nt][2] - mn_hi));
            uint32_t p3 = f2tf(__expf(sacc[nt][3] - mn_hi));
            sum_lo += __uint_as_float(p0) + __uint_as_float(p1);
            sum_hi += __uint_as_float(p2) + __uint_as_float(p3);
            sacc[nt][0] = __uint_as_float(p0);
            sacc[nt][1] = __uint_as_float(p1);
            sacc[nt][2] = __uint_as_float(p2);
            sacc[nt][3] = __uint_as_float(p3);
        }
        sum_lo += __shfl_xor_sync(0xffffffffu, sum_lo, 1);
        sum_lo += __shfl_xor_sync(0xffffffffu, sum_lo, 2);
        sum_hi += __shfl_xor_sync(0xffffffffu, sum_hi, 1);
        sum_hi += __shfl_xor_sync(0xffffffffu, sum_hi, 2);
        l_lo = l_lo * al_lo + sum_lo;
        l_hi = l_hi * al_hi + sum_hi;

        // ---- P c-frag -> per-warp smem strip (warp-private, syncwarp only) ----
        __syncwarp();
        #pragma unroll
        for (int nt = 0; nt < 8; nt++) {
            const int pc = nt * 8 + 2 * tig;
            *(float2*)&Pw[g * PW_STRIDE + pc] =
                make_float2(sacc[nt][0], sacc[nt][1]);
            *(float2*)&Pw[(g + 8) * PW_STRIDE + pc] =
                make_float2(sacc[nt][2], sacc[nt][3]);
        }
        __syncwarp();

        // ---- phase 2: O = O*alpha + P @ V, full width (16 n-tiles) ----
        #pragma unroll
        for (int nt = 0; nt < 16; nt++) {
            o[nt][0] *= al_lo; o[nt][1] *= al_lo;
            o[nt][2] *= al_hi; o[nt][3] *= al_hi;
        }
        #pragma unroll
        for (int ks = 0; ks < 8; ks++) {
            const int k0 = ks * 8;
            uint32_t ap[4];
            ap[0] = Pw[g * PW_STRIDE + k0 + tig];
            ap[1] = Pw[(g + 8) * PW_STRIDE + k0 + tig];
            ap[2] = Pw[g * PW_STRIDE + k0 + tig + 4];
            ap[3] = Pw[(g + 8) * PW_STRIDE + k0 + tig + 4];
            #pragma unroll
            for (int nt = 0; nt < 16; nt++) {
                const int d = nt * 8 + g;
                uint32_t bv[2];
                bv[0] = Vs[(k0 + tig) * VS_STRIDE + d];
                bv[1] = Vs[(k0 + tig + 4) * VS_STRIDE + d];
                mma8(o[nt], ap, bv);
            }
        }
    }

    // ---- epilogue: normalize, store ----
    {
        const float inv_lo = 1.0f / l_lo;
        const float inv_hi = 1.0f / l_hi;
        const int row_lo = qb * BQ + wid * 16 + g;
        float* op_lo = out + (size_t)(b * SEQ + row_lo) * OUTD + DIMS;
        float* op_hi = out + (size_t)(b * SEQ + row_lo + 8) * OUTD + DIMS;
        #pragma unroll
        for (int nt = 0; nt < 16; nt++) {
            const int d = nt * 8 + 2 * tig;
            *(float2*)(op_lo + d) = make_float2(o[nt][0] * inv_lo, o[nt][1] * inv_lo);
            *(float2*)(op_hi + d) = make_float2(o[nt][2] * inv_hi, o[nt][3] * inv_hi);
        }
    }
}

// ---------------------------------------------------------------------------
// Launch
// ---------------------------------------------------------------------------
extern "C" void kernel_launch(void* const* d_in, const int* in_sizes, int n_in,
                              void* d_out, int out_size) {
    const float* x   = (const float*)d_in[0];
    const float* Wk  = (const float*)d_in[1];
    const float* bk  = (const float*)d_in[2];
    const float* Wv  = (const float*)d_in[3];
    const float* bv  = (const float*)d_in[4];
    float* out = (float*)d_out;

    proj_tc_kernel<<<dim3(NROWS / 128, 2), 256>>>(x, Wk, bk, Wv, bv, out);

    cudaFuncSetAttribute(attn_tc_kernel, cudaFuncAttributeMaxDynamicSharedMemorySize,
                         ATTN_SMEM_BYTES);
    attn_tc_kernel<<<BATCH * (SEQ / BQ), 128, ATTN_SMEM_BYTES>>>(out);
}